// round 11
// baseline (speedup 1.0000x reference)
#include <cuda_runtime.h>
#include <cstdint>

#define BATCH 4
#define SEQ   2048
#define CIN   1024
#define HID   1024

// ---------------- scratch (__device__ globals; alloc APIs forbidden) -------
__device__ float g_qp [BATCH * SEQ * HID];          // 32 MB (tf32-rounded, pre-scaled 2^-5)
__device__ float g_kp [BATCH * SEQ * HID];          // 32 MB (tf32-rounded)
__device__ float g_vp [BATCH * SEQ * HID];          // 32 MB (tf32-rounded)
__device__ float g_S  [(long)BATCH * SEQ * SEQ];    // 64 MB

// ---------------- helpers ---------------------------------------------------
__device__ __forceinline__ uint32_t smem_u32(const void* p) {
    uint32_t r;
    asm("{ .reg .u64 t; cvta.to.shared.u64 t, %1; cvt.u32.u64 %0, t; }"
        : "=r"(r) : "l"(p));
    return r;
}
__device__ __forceinline__ void cpa16(uint32_t dst, const void* src) {
    asm volatile("cp.async.cg.shared.global [%0], [%1], 16;" :: "r"(dst), "l"(src));
}
__device__ __forceinline__ uint32_t f2tf(float x) {
    uint32_t r;
    asm("cvt.rna.tf32.f32 %0, %1;" : "=r"(r) : "f"(x));
    return r;
}
__device__ __forceinline__ float roundtf(float x) { return __uint_as_float(f2tf(x)); }
__device__ __forceinline__ void mma_tf32(float* c, const uint32_t* a, const uint32_t* b) {
    asm volatile("mma.sync.aligned.m16n8k8.row.col.f32.tf32.tf32.f32 "
                 "{%0,%1,%2,%3}, {%4,%5,%6,%7}, {%8,%9}, {%0,%1,%2,%3};"
                 : "+f"(c[0]), "+f"(c[1]), "+f"(c[2]), "+f"(c[3])
                 : "r"(a[0]), "r"(a[1]), "r"(a[2]), "r"(a[3]),
                   "r"(b[0]), "r"(b[1]));
}

// ---------------- tensor-core tf32 GEMM core --------------------------------
// C[M,N] = A[M,K] @ Bop, 128x128 CTA tile, BK=32, 3-stage cp.async pipeline,
// 8 warps (4x2), warp tile 32x64 (occupancy-optimized: ~125 regs/thread,
// 2 CTAs/SM = 16 warps to cover the LDS->MMA latency chain).
//   BNN=false: Bop = B[N,K]^T (B row-major K-contiguous).
//   BNN=true : Bop = B[K,N]   (B row-major N-contiguous).
#define NSTAGE      3
#define STAGE_FLTS  8192          // A 4096 + B 4096 floats (32 KB)
#define GEMM_SMEM   (NSTAGE * STAGE_FLTS * 4)   // 98304 B
#define GTHREADS    256

template<bool CVTA, bool ROUND_OUT, bool BNN>
__device__ __forceinline__
void gemm_body(const float* __restrict__ A, const float* __restrict__ B,
               float* __restrict__ C, int ldA, int ldB, int ldC,
               int KT, int bm, int bn, float alphaOut)
{
    extern __shared__ float sm[];
    const uint32_t sbase = smem_u32(sm);
    const int tid  = threadIdx.x;
    const int lane = tid & 31;
    const int wid  = tid >> 5;        // 0..7
    const int wm = (wid >> 1) * 32;   // 4 warp rows
    const int wn = (wid & 1) * 64;    // 2 warp cols
    const int qr = lane >> 2;         // 0..7
    const int qc = lane & 3;          // 0..3
    const int xm = qr << 2;

    // ---- loader bases (strength-reduced; 4 vec4 per tile per thread) ----
    // A (and NT-B): rows arow+32t, t=0..3; row&7 invariant -> smem step 4096B.
    const int arow = tid >> 3;            // 0..31
    const int akq  = (tid & 7) * 4;
    const float* Abase = A + (long)(bm * 128 + arow) * ldA + akq;
    const long aStride = (long)32 * ldA;
    const uint32_t adst0 = sbase + (uint32_t)(arow * 32 + (akq ^ ((arow & 7) << 2))) * 4;

    const float* Bbase; long bStride; long bStageStep; uint32_t bdst0;
    if (BNN) {   // tile [k][n], k = bk+8t (k&3 invariant), swizzle n^=((k&3)<<3)
        const int bk  = tid >> 5;         // 0..7
        const int bn4 = (tid & 31) * 4;
        Bbase = B + (long)bk * ldB + bn * 128 + bn4;
        bStride = (long)8 * ldB;
        bStageStep = (long)32 * ldB;
        bdst0 = sbase + 16384u + (uint32_t)(bk * 128 + (bn4 ^ ((bk & 3) << 3))) * 4;
    } else {     // tile [n][k], same geometry as A
        Bbase = B + (long)(bn * 128 + arow) * ldB + akq;
        bStride = (long)32 * ldB;
        bStageStep = 32;
        bdst0 = sbase + 16384u + (uint32_t)(arow * 32 + (akq ^ ((arow & 7) << 2))) * 4;
    }

    auto issue_stage = [&](int s) {
        const uint32_t soff = (uint32_t)((s % NSTAGE) * (STAGE_FLTS * 4));
        const float* ap = Abase + s * 32;
        uint32_t ad = adst0 + soff;
#pragma unroll
        for (int t = 0; t < 4; t++) { cpa16(ad, ap); ap += aStride; ad += 4096; }
        const float* bp = Bbase + s * bStageStep;
        uint32_t bd = bdst0 + soff;
#pragma unroll
        for (int t = 0; t < 4; t++) { cpa16(bd, bp); bp += bStride; bd += 4096; }
    };

    // NN fragment column pre-swizzle
    int npr[8];
    if (BNN) {
#pragma unroll
        for (int nt = 0; nt < 8; nt++)
            npr[nt] = (wn + nt * 8 + qr) ^ (qc << 3);
    }

    auto load_frags = [&](const float* As, const float* Bs, int ks,
                          uint32_t af[2][4], uint32_t bf[8][2]) {
        const int k0 = ks * 8;
        const int c0 = (k0 + qc) ^ xm;
        const int c1 = (k0 + 4 + qc) ^ xm;
#pragma unroll
        for (int mt = 0; mt < 2; mt++) {
            int r  = wm + mt * 16 + qr;
            int r8 = r + 8;
            if (CVTA) {
                af[mt][0] = f2tf(As[r  * 32 + c0]);
                af[mt][1] = f2tf(As[r8 * 32 + c0]);
                af[mt][2] = f2tf(As[r  * 32 + c1]);
                af[mt][3] = f2tf(As[r8 * 32 + c1]);
            } else {
                af[mt][0] = __float_as_uint(As[r  * 32 + c0]);
                af[mt][1] = __float_as_uint(As[r8 * 32 + c0]);
                af[mt][2] = __float_as_uint(As[r  * 32 + c1]);
                af[mt][3] = __float_as_uint(As[r8 * 32 + c1]);
            }
        }
#pragma unroll
        for (int nt = 0; nt < 8; nt++) {
            if (BNN) {
                bf[nt][0] = __float_as_uint(Bs[(k0 + qc)     * 128 + npr[nt]]);
                bf[nt][1] = __float_as_uint(Bs[(k0 + 4 + qc) * 128 + npr[nt]]);
            } else {
                int n = wn + nt * 8 + qr;
                bf[nt][0] = __float_as_uint(Bs[n * 32 + c0]);
                bf[nt][1] = __float_as_uint(Bs[n * 32 + c1]);
            }
        }
    };

    float acc[2][8][4];
#pragma unroll
    for (int mt = 0; mt < 2; mt++)
#pragma unroll
        for (int nt = 0; nt < 8; nt++)
#pragma unroll
            for (int i = 0; i < 4; i++) acc[mt][nt][i] = 0.0f;

    // prologue: stages 0 and 1
#pragma unroll
    for (int s = 0; s < 2; s++) {
        issue_stage(s);
        asm volatile("cp.async.commit_group;" ::: "memory");
    }

    for (int kt = 0; kt < KT; kt++) {
        asm volatile("cp.async.wait_group 1;" ::: "memory");
        __syncthreads();

        const float* As = sm + (kt % NSTAGE) * STAGE_FLTS;
        const float* Bs = As + 4096;

        // prefetch stage kt+2: gmem loads overlap the whole MMA body
        int sf = kt + 2;
        if (sf < KT) issue_stage(sf);
        asm volatile("cp.async.commit_group;" ::: "memory");

#pragma unroll
        for (int ks = 0; ks < 4; ks++) {
            uint32_t af[2][4], bf[8][2];
            load_frags(As, Bs, ks, af, bf);
#pragma unroll
            for (int mt = 0; mt < 2; mt++)
#pragma unroll
                for (int nt = 0; nt < 8; nt++)
                    mma_tf32(acc[mt][nt], af[mt], bf[nt]);
        }
    }

#pragma unroll
    for (int mt = 0; mt < 2; mt++) {
        int r = bm * 128 + wm + mt * 16 + qr;
#pragma unroll
        for (int nt = 0; nt < 8; nt++) {
            int col = bn * 128 + wn + nt * 8 + 2 * qc;
            float o0 = acc[mt][nt][0] * alphaOut, o1 = acc[mt][nt][1] * alphaOut;
            float o2 = acc[mt][nt][2] * alphaOut, o3 = acc[mt][nt][3] * alphaOut;
            if (ROUND_OUT) { o0 = roundtf(o0); o1 = roundtf(o1);
                             o2 = roundtf(o2); o3 = roundtf(o3); }
            *(float2*)&C[(long)r * ldC + col]       = make_float2(o0, o1);
            *(float2*)&C[(long)(r + 8) * ldC + col] = make_float2(o2, o3);
        }
    }
}

// q/k projections (NN: W[C][H] read directly):
// z=0 (q,Wq)->qp (pre-scaled 2^-5), z=1 (k,Wk)->kp.
__global__ __launch_bounds__(GTHREADS, 2)
void proj_qk(const float* __restrict__ qin, const float* __restrict__ kin,
             const float* __restrict__ Wq, const float* __restrict__ Wk,
             float* __restrict__ qp, float* __restrict__ kp)
{
    const float* A; const float* B; float* C; float alpha = 1.0f;
    if (blockIdx.z == 0) { A = qin; B = Wq; C = qp; alpha = 1.0f / 32.0f; }
    else                 { A = kin; B = Wk; C = kp; }
    gemm_body<true, true, true>(A, B, C, CIN, HID, HID, CIN / 32,
                                blockIdx.y, blockIdx.x, alpha);
}

// Merged launch: blockIdx.x < 136 -> S block (triangular, heavy-first);
// blockIdx.x >= 136 -> proj_v block (vp = v @ Wq, faithful bug) filling
// the S launch's wave tails.
__global__ __launch_bounds__(GTHREADS, 2)
void s_plus_projv(const float* __restrict__ qp, const float* __restrict__ kp,
                  float* __restrict__ S, const float* __restrict__ vin,
                  const float* __restrict__ Wq, float* __restrict__ vp)
{
    if (blockIdx.x < 136) {
        int idx = 135 - blockIdx.x;       // heavy (high-bm) first
        int acc = 0, bm = 0;
        while (acc + bm + 1 <= idx) { acc += bm + 1; bm++; }
        int bn = idx - acc;
        const long ob = (long)blockIdx.z * SEQ * HID;
        gemm_body<false, false, false>(qp + ob, kp + ob,
                                       S + (long)blockIdx.z * SEQ * SEQ,
                                       HID, HID, SEQ, HID / 32, bm, bn, 1.0f);
    } else {
        int id = (int)(blockIdx.x - 136) + (int)blockIdx.z * 128;  // 0..511
        int bm = id >> 3;                 // 0..63
        int bn = id & 7;                  // 0..7
        gemm_body<true, true, true>(vin, Wq, vp, CIN, HID, HID, CIN / 32,
                                    bm, bn, 1.0f);
    }
}

// out = P @ vp (NN), K causally limited, heavy blocks first.
__global__ __launch_bounds__(GTHREADS, 2)
void pv_gemm(const float* __restrict__ S, const float* __restrict__ vp,
             float* __restrict__ out)
{
    const int bm = (int)(gridDim.y - 1 - blockIdx.y);   // heavy first
    const int bn = blockIdx.x;
    const int KT = (bm + 1) * 4;
    gemm_body<false, false, true>(S + (long)blockIdx.z * SEQ * SEQ,
                                  vp + (long)blockIdx.z * SEQ * HID,
                                  out + (long)blockIdx.z * SEQ * HID,
                                  SEQ, HID, HID, KT, bm, bn, 1.0f);
}

// ---------------- single-pass causal softmax (input pre-scaled) ------------
__global__ __launch_bounds__(256)
void softmax_fast(float* __restrict__ S)
{
    const int t = blockIdx.x, b = blockIdx.y;
    float* row = S + ((long)b * SEQ + t) * SEQ;
    const int n = t + 1;
    const int limit = ((t >> 7) + 1) << 7;
    const int tid = threadIdx.x;
    const int lane = tid & 31, wid = tid >> 5;

    __shared__ float redm[8], reds[8];

    float r[8];
#pragma unroll
    for (int j = 0; j < 8; j++) {
        int i = tid + j * 256;
        r[j] = (i < n) ? row[i] : -1e30f;
    }

    float m = -1e30f;
#pragma unroll
    for (int j = 0; j < 8; j++) m = fmaxf(m, r[j]);
#pragma unroll
    for (int o = 16; o > 0; o >>= 1) m = fmaxf(m, __shfl_xor_sync(~0u, m, o));
    if (lane == 0) redm[wid] = m;
    __syncthreads();
#pragma unroll
    for (int j = 0; j < 8; j++) m = fmaxf(m, redm[j]);

    float sum = 0.0f;
#pragma unroll
    for (int j = 0; j < 8; j++) { r[j] = __expf(r[j] - m); sum += r[j]; }
#pragma unroll
    for (int o = 16; o > 0; o >>= 1) sum += __shfl_xor_sync(~0u, sum, o);
    if (lane == 0) reds[wid] = sum;
    __syncthreads();
    sum = 0.0f;
#pragma unroll
    for (int j = 0; j < 8; j++) sum += reds[j];
    const float inv = 1.0f / sum;

#pragma unroll
    for (int j = 0; j < 8; j++) {
        int i = tid + j * 256;
        if (i < limit) row[i] = (i < n) ? roundtf(r[j] * inv) : 0.0f;
    }
}

// ---------------- launch ---------------------------------------------------
extern "C" void kernel_launch(void* const* d_in, const int* in_sizes, int n_in,
                              void* d_out, int out_size)
{
    const float* kin = (const float*)d_in[1];
    const float* qin = (const float*)d_in[2];
    const float* vin = (const float*)d_in[3];
    const float* Wk  = (const float*)d_in[4];
    const float* Wq  = (const float*)d_in[5];
    float* out = (float*)d_out;

    float *qp, *kp, *vp, *S;
    cudaGetSymbolAddress((void**)&qp, g_qp);
    cudaGetSymbolAddress((void**)&kp, g_kp);
    cudaGetSymbolAddress((void**)&vp, g_vp);
    cudaGetSymbolAddress((void**)&S,  g_S);

    cudaFuncSetAttribute(proj_qk,      cudaFuncAttributeMaxDynamicSharedMemorySize, GEMM_SMEM);
    cudaFuncSetAttribute(s_plus_projv, cudaFuncAttributeMaxDynamicSharedMemorySize, GEMM_SMEM);
    cudaFuncSetAttribute(pv_gemm,      cudaFuncAttributeMaxDynamicSharedMemorySize, GEMM_SMEM);

    const int M = BATCH * SEQ;                 // 8192
    dim3 blk(256);
    dim3 gblk(GTHREADS);

    // q/k projections (v projection rides inside the S launch)
    proj_qk<<<dim3(HID / 128, M / 128, 2), gblk, GEMM_SMEM>>>(qin, kin, Wq, Wk, qp, kp);

    // S = qp @ kp^T fused with proj_v (fills S's wave tails)
    s_plus_projv<<<dim3(136 + 128, 1, BATCH), gblk, GEMM_SMEM>>>(qp, kp, S, vin, Wq, vp);

    // softmax (scale pre-folded into qp), zeros upper triangle per 128-block
    softmax_fast<<<dim3(SEQ, BATCH), blk>>>(S);

    // out = P @ vp, K causally limited
    pv_gemm<<<dim3(HID / 128, SEQ / 128, BATCH), gblk, GEMM_SMEM>>>(S, vp, out);
}

// round 12
// speedup vs baseline: 1.1098x; 1.1098x over previous
#include <cuda_runtime.h>
#include <cstdint>

#define BATCH 4
#define SEQ   2048
#define CIN   1024
#define HID   1024

// ---------------- scratch (__device__ globals; alloc APIs forbidden) -------
__device__ float g_qp [BATCH * SEQ * HID];          // 32 MB (tf32-rounded, pre-scaled 2^-5)
__device__ float g_kp [BATCH * SEQ * HID];          // 32 MB (tf32-rounded)
__device__ float g_vp [BATCH * SEQ * HID];          // 32 MB (tf32-rounded)
__device__ float g_S  [(long)BATCH * SEQ * SEQ];    // 64 MB

// ---------------- helpers ---------------------------------------------------
__device__ __forceinline__ uint32_t smem_u32(const void* p) {
    uint32_t r;
    asm("{ .reg .u64 t; cvta.to.shared.u64 t, %1; cvt.u32.u64 %0, t; }"
        : "=r"(r) : "l"(p));
    return r;
}
__device__ __forceinline__ void cpa16(uint32_t dst, const void* src) {
    asm volatile("cp.async.cg.shared.global [%0], [%1], 16;" :: "r"(dst), "l"(src));
}
__device__ __forceinline__ uint32_t f2tf(float x) {
    uint32_t r;
    asm("cvt.rna.tf32.f32 %0, %1;" : "=r"(r) : "f"(x));
    return r;
}
__device__ __forceinline__ float roundtf(float x) { return __uint_as_float(f2tf(x)); }
__device__ __forceinline__ void mma_tf32(float* c, const uint32_t* a, const uint32_t* b) {
    asm volatile("mma.sync.aligned.m16n8k8.row.col.f32.tf32.tf32.f32 "
                 "{%0,%1,%2,%3}, {%4,%5,%6,%7}, {%8,%9}, {%0,%1,%2,%3};"
                 : "+f"(c[0]), "+f"(c[1]), "+f"(c[2]), "+f"(c[3])
                 : "r"(a[0]), "r"(a[1]), "r"(a[2]), "r"(a[3]),
                   "r"(b[0]), "r"(b[1]));
}

// ---------------- tensor-core tf32 GEMM core (R10 config: best) -------------
// C[M,N] = A[M,K] @ Bop, 128x128 CTA tile, BK=32, 3-stage cp.async pipeline,
// 4 warps (2x2), warp tile 64x64, double-buffered fragments.
//   BNN=false: Bop = B[N,K]^T (B row-major K-contiguous).
//   BNN=true : Bop = B[K,N]   (B row-major N-contiguous).
#define NSTAGE      3
#define STAGE_FLTS  8192          // A 4096 + B 4096 floats (32 KB)
#define GEMM_SMEM   (NSTAGE * STAGE_FLTS * 4)   // 98304 B
#define GTHREADS    128

template<bool CVTA, bool ROUND_OUT, bool BNN>
__device__ __forceinline__
void gemm_body(const float* __restrict__ A, const float* __restrict__ B,
               float* __restrict__ C, int ldA, int ldB, int ldC,
               int KT, int bm, int bn, float alphaOut)
{
    extern __shared__ float sm[];
    const uint32_t sbase = smem_u32(sm);
    const int tid  = threadIdx.x;
    const int lane = tid & 31;
    const int wid  = tid >> 5;        // 0..3
    const int wm = (wid >> 1) * 64;
    const int wn = (wid & 1) * 64;
    const int qr = lane >> 2;         // 0..7
    const int qc = lane & 3;          // 0..3
    const int xm = qr << 2;

    // ---- loader bases (strength-reduced) ----
    const int arow = tid >> 3;            // 0..15
    const int akq  = (tid & 7) * 4;
    const float* Abase = A + (long)(bm * 128 + arow) * ldA + akq;
    const long aStride = (long)16 * ldA;
    const uint32_t adst0 = sbase + (uint32_t)(arow * 32 + (akq ^ ((arow & 7) << 2))) * 4;

    const float* Bbase; long bStride; long bStageStep; uint32_t bdst0;
    if (BNN) {   // tile [k][n], swizzle n^=((k&3)<<3)
        const int bk  = tid >> 5;         // 0..3
        const int bn4 = (tid & 31) * 4;
        Bbase = B + (long)bk * ldB + bn * 128 + bn4;
        bStride = (long)4 * ldB;
        bStageStep = (long)32 * ldB;
        bdst0 = sbase + 16384u + (uint32_t)(bk * 128 + (bn4 ^ ((bk & 3) << 3))) * 4;
    } else {     // tile [n][k], same geometry as A
        Bbase = B + (long)(bn * 128 + arow) * ldB + akq;
        bStride = (long)16 * ldB;
        bStageStep = 32;
        bdst0 = sbase + 16384u + (uint32_t)(arow * 32 + (akq ^ ((arow & 7) << 2))) * 4;
    }

    auto issue_stage = [&](int s) {
        const uint32_t soff = (uint32_t)((s % NSTAGE) * (STAGE_FLTS * 4));
        const float* ap = Abase + s * 32;
        uint32_t ad = adst0 + soff;
#pragma unroll
        for (int t = 0; t < 8; t++) { cpa16(ad, ap); ap += aStride; ad += 2048; }
        const float* bp = Bbase + s * bStageStep;
        uint32_t bd = bdst0 + soff;
#pragma unroll
        for (int t = 0; t < 8; t++) { cpa16(bd, bp); bp += bStride; bd += 2048; }
    };

    // NN fragment column pre-swizzle
    int npr[8];
    if (BNN) {
#pragma unroll
        for (int nt = 0; nt < 8; nt++)
            npr[nt] = (wn + nt * 8 + qr) ^ (qc << 3);
    }

    auto load_frags = [&](const float* As, const float* Bs, int ks,
                          uint32_t af[4][4], uint32_t bf[8][2]) {
        const int k0 = ks * 8;
        const int c0 = (k0 + qc) ^ xm;
        const int c1 = (k0 + 4 + qc) ^ xm;
#pragma unroll
        for (int mt = 0; mt < 4; mt++) {
            int r  = wm + mt * 16 + qr;
            int r8 = r + 8;
            if (CVTA) {
                af[mt][0] = f2tf(As[r  * 32 + c0]);
                af[mt][1] = f2tf(As[r8 * 32 + c0]);
                af[mt][2] = f2tf(As[r  * 32 + c1]);
                af[mt][3] = f2tf(As[r8 * 32 + c1]);
            } else {
                af[mt][0] = __float_as_uint(As[r  * 32 + c0]);
                af[mt][1] = __float_as_uint(As[r8 * 32 + c0]);
                af[mt][2] = __float_as_uint(As[r  * 32 + c1]);
                af[mt][3] = __float_as_uint(As[r8 * 32 + c1]);
            }
        }
#pragma unroll
        for (int nt = 0; nt < 8; nt++) {
            if (BNN) {
                bf[nt][0] = __float_as_uint(Bs[(k0 + qc)     * 128 + npr[nt]]);
                bf[nt][1] = __float_as_uint(Bs[(k0 + 4 + qc) * 128 + npr[nt]]);
            } else {
                int n = wn + nt * 8 + qr;
                bf[nt][0] = __float_as_uint(Bs[n * 32 + c0]);
                bf[nt][1] = __float_as_uint(Bs[n * 32 + c1]);
            }
        }
    };

    float acc[4][8][4];
#pragma unroll
    for (int mt = 0; mt < 4; mt++)
#pragma unroll
        for (int nt = 0; nt < 8; nt++)
#pragma unroll
            for (int i = 0; i < 4; i++) acc[mt][nt][i] = 0.0f;

    auto run_mma = [&](uint32_t af[4][4], uint32_t bf[8][2]) {
#pragma unroll
        for (int mt = 0; mt < 4; mt++)
#pragma unroll
            for (int nt = 0; nt < 8; nt++)
                mma_tf32(acc[mt][nt], af[mt], bf[nt]);
    };

    // prologue: stages 0 and 1
#pragma unroll
    for (int s = 0; s < 2; s++) {
        issue_stage(s);
        asm volatile("cp.async.commit_group;" ::: "memory");
    }

    for (int kt = 0; kt < KT; kt++) {
        asm volatile("cp.async.wait_group 1;" ::: "memory");
        __syncthreads();

        const float* As = sm + (kt % NSTAGE) * STAGE_FLTS;
        const float* Bs = As + 4096;

        uint32_t afA[4][4], bfA[8][2], afB[4][4], bfB[8][2];
        load_frags(As, Bs, 0, afA, bfA);

        // prefetch stage kt+2: gmem loads overlap the whole MMA body
        int sf = kt + 2;
        if (sf < KT) issue_stage(sf);
        asm volatile("cp.async.commit_group;" ::: "memory");

        load_frags(As, Bs, 1, afB, bfB);
        run_mma(afA, bfA);
        load_frags(As, Bs, 2, afA, bfA);
        run_mma(afB, bfB);
        load_frags(As, Bs, 3, afB, bfB);
        run_mma(afA, bfA);
        run_mma(afB, bfB);
    }

#pragma unroll
    for (int mt = 0; mt < 4; mt++) {
        int r = bm * 128 + wm + mt * 16 + qr;
#pragma unroll
        for (int nt = 0; nt < 8; nt++) {
            int col = bn * 128 + wn + nt * 8 + 2 * qc;
            float o0 = acc[mt][nt][0] * alphaOut, o1 = acc[mt][nt][1] * alphaOut;
            float o2 = acc[mt][nt][2] * alphaOut, o3 = acc[mt][nt][3] * alphaOut;
            if (ROUND_OUT) { o0 = roundtf(o0); o1 = roundtf(o1);
                             o2 = roundtf(o2); o3 = roundtf(o3); }
            *(float2*)&C[(long)r * ldC + col]       = make_float2(o0, o1);
            *(float2*)&C[(long)(r + 8) * ldC + col] = make_float2(o2, o3);
        }
    }
}

// q/k projections (NN: W[C][H] read directly):
// z=0 (q,Wq)->qp (pre-scaled 2^-5), z=1 (k,Wk)->kp.
__global__ __launch_bounds__(GTHREADS, 2)
void proj_qk(const float* __restrict__ qin, const float* __restrict__ kin,
             const float* __restrict__ Wq, const float* __restrict__ Wk,
             float* __restrict__ qp, float* __restrict__ kp)
{
    const float* A; const float* B; float* C; float alpha = 1.0f;
    if (blockIdx.z == 0) { A = qin; B = Wq; C = qp; alpha = 1.0f / 32.0f; }
    else                 { A = kin; B = Wk; C = kp; }
    gemm_body<true, true, true>(A, B, C, CIN, HID, HID, CIN / 32,
                                blockIdx.y, blockIdx.x, alpha);
}

// v projection (runs on a low-priority side stream; fills wave tails of the
// critical proj_qk -> S -> softmax chain). vp = v @ Wq (faithful bug).
__global__ __launch_bounds__(GTHREADS, 2)
void proj_v(const float* __restrict__ vin, const float* __restrict__ Wq,
            float* __restrict__ vp)
{
    gemm_body<true, true, true>(vin, Wq, vp, CIN, HID, HID, CIN / 32,
                                blockIdx.y, blockIdx.x, 1.0f);
}

// S = qp @ kp^T (scale folded into qp), triangular grid, heavy blocks first.
__global__ __launch_bounds__(GTHREADS, 2)
void s_gemm(const float* __restrict__ qp, const float* __restrict__ kp,
            float* __restrict__ S)
{
    int idx = 135 - blockIdx.x;           // heavy (high-bm) first
    int acc = 0, bm = 0;
    while (acc + bm + 1 <= idx) { acc += bm + 1; bm++; }
    int bn = idx - acc;
    const long ob = (long)blockIdx.z * SEQ * HID;
    gemm_body<false, false, false>(qp + ob, kp + ob,
                                   S + (long)blockIdx.z * SEQ * SEQ,
                                   HID, HID, SEQ, HID / 32, bm, bn, 1.0f);
}

// out = P @ vp (NN), K causally limited, heavy blocks first.
__global__ __launch_bounds__(GTHREADS, 2)
void pv_gemm(const float* __restrict__ S, const float* __restrict__ vp,
             float* __restrict__ out)
{
    const int bm = (int)(gridDim.y - 1 - blockIdx.y);   // heavy first
    const int bn = blockIdx.x;
    const int KT = (bm + 1) * 4;
    gemm_body<false, false, true>(S + (long)blockIdx.z * SEQ * SEQ,
                                  vp + (long)blockIdx.z * SEQ * HID,
                                  out + (long)blockIdx.z * SEQ * HID,
                                  SEQ, HID, HID, KT, bm, bn, 1.0f);
}

// ---------------- single-pass causal softmax (input pre-scaled) ------------
__global__ __launch_bounds__(256)
void softmax_fast(float* __restrict__ S)
{
    const int t = blockIdx.x, b = blockIdx.y;
    float* row = S + ((long)b * SEQ + t) * SEQ;
    const int n = t + 1;
    const int limit = ((t >> 7) + 1) << 7;
    const int tid = threadIdx.x;
    const int lane = tid & 31, wid = tid >> 5;

    __shared__ float redm[8], reds[8];

    float r[8];
#pragma unroll
    for (int j = 0; j < 8; j++) {
        int i = tid + j * 256;
        r[j] = (i < n) ? row[i] : -1e30f;
    }

    float m = -1e30f;
#pragma unroll
    for (int j = 0; j < 8; j++) m = fmaxf(m, r[j]);
#pragma unroll
    for (int o = 16; o > 0; o >>= 1) m = fmaxf(m, __shfl_xor_sync(~0u, m, o));
    if (lane == 0) redm[wid] = m;
    __syncthreads();
#pragma unroll
    for (int j = 0; j < 8; j++) m = fmaxf(m, redm[j]);

    float sum = 0.0f;
#pragma unroll
    for (int j = 0; j < 8; j++) { r[j] = __expf(r[j] - m); sum += r[j]; }
#pragma unroll
    for (int o = 16; o > 0; o >>= 1) sum += __shfl_xor_sync(~0u, sum, o);
    if (lane == 0) reds[wid] = sum;
    __syncthreads();
    sum = 0.0f;
#pragma unroll
    for (int j = 0; j < 8; j++) sum += reds[j];
    const float inv = 1.0f / sum;

#pragma unroll
    for (int j = 0; j < 8; j++) {
        int i = tid + j * 256;
        if (i < limit) row[i] = (i < n) ? roundtf(r[j] * inv) : 0.0f;
    }
}

// ---------------- launch (fork-join graph: proj_v on a side stream) --------
extern "C" void kernel_launch(void* const* d_in, const int* in_sizes, int n_in,
                              void* d_out, int out_size)
{
    const float* kin = (const float*)d_in[1];
    const float* qin = (const float*)d_in[2];
    const float* vin = (const float*)d_in[3];
    const float* Wk  = (const float*)d_in[4];
    const float* Wq  = (const float*)d_in[5];
    float* out = (float*)d_out;

    float *qp, *kp, *vp, *S;
    cudaGetSymbolAddress((void**)&qp, g_qp);
    cudaGetSymbolAddress((void**)&kp, g_kp);
    cudaGetSymbolAddress((void**)&vp, g_vp);
    cudaGetSymbolAddress((void**)&S,  g_S);

    cudaFuncSetAttribute(proj_qk, cudaFuncAttributeMaxDynamicSharedMemorySize, GEMM_SMEM);
    cudaFuncSetAttribute(proj_v,  cudaFuncAttributeMaxDynamicSharedMemorySize, GEMM_SMEM);
    cudaFuncSetAttribute(s_gemm,  cudaFuncAttributeMaxDynamicSharedMemorySize, GEMM_SMEM);
    cudaFuncSetAttribute(pv_gemm, cudaFuncAttributeMaxDynamicSharedMemorySize, GEMM_SMEM);

    const int M = BATCH * SEQ;                 // 8192
    dim3 blk(256);
    dim3 gblk(GTHREADS);

    // side stream (low priority so it only backfills idle SM slots) + events.
    // Created per call and intentionally not destroyed: kernel_launch runs only
    // a handful of times (correctness + one capture); destroying during capture
    // is hazardous and these objects hold no device memory.
    int loPri = 0, hiPri = 0;
    cudaDeviceGetStreamPriorityRange(&loPri, &hiPri);
    cudaStream_t s2;
    cudaStreamCreateWithPriority(&s2, cudaStreamNonBlocking, loPri);
    cudaEvent_t eFork, eJoin;
    cudaEventCreateWithFlags(&eFork, cudaEventDisableTiming);
    cudaEventCreateWithFlags(&eJoin, cudaEventDisableTiming);

    // fork: bring s2 into the captured graph
    cudaEventRecord(eFork, 0);
    cudaStreamWaitEvent(s2, eFork, 0);

    // critical chain on the main stream
    proj_qk<<<dim3(HID / 128, M / 128, 2), gblk, GEMM_SMEM>>>(qin, kin, Wq, Wk, qp, kp);

    // independent v-projection on the side stream (backfills wave tails)
    proj_v<<<dim3(HID / 128, M / 128, 1), gblk, GEMM_SMEM, s2>>>(vin, Wq, vp);
    cudaEventRecord(eJoin, s2);

    s_gemm<<<dim3(136, 1, BATCH), gblk, GEMM_SMEM>>>(qp, kp, S);
    softmax_fast<<<dim3(SEQ, BATCH), blk>>>(S);

    // join: pv needs vp
    cudaStreamWaitEvent(0, eJoin, 0);
    pv_gemm<<<dim3(HID / 128, SEQ / 128, BATCH), gblk, GEMM_SMEM>>>(S, vp, out);
}

// round 13
// speedup vs baseline: 1.1305x; 1.0186x over previous
#include <cuda_runtime.h>
#include <cstdint>

#define BATCH 4
#define SEQ   2048
#define CIN   1024
#define HID   1024

// ---------------- scratch (__device__ globals; alloc APIs forbidden) -------
__device__ float g_qp  [BATCH * SEQ * HID];         // 32 MB (tf32-rounded, pre-scaled 2^-5)
__device__ float g_kp  [BATCH * SEQ * HID];         // 32 MB (tf32-rounded)
__device__ float g_vp  [BATCH * SEQ * HID];         // 32 MB (tf32-rounded)
__device__ float g_P   [(long)BATCH * SEQ * SEQ];   // 64 MB (unnormalized exp'd probs)
__device__ float g_psum[BATCH * 16 * SEQ];          // 512 KB (per-block partial row sums)

// ---------------- helpers ---------------------------------------------------
__device__ __forceinline__ uint32_t smem_u32(const void* p) {
    uint32_t r;
    asm("{ .reg .u64 t; cvta.to.shared.u64 t, %1; cvt.u32.u64 %0, t; }"
        : "=r"(r) : "l"(p));
    return r;
}
__device__ __forceinline__ void cpa16(uint32_t dst, const void* src) {
    asm volatile("cp.async.cg.shared.global [%0], [%1], 16;" :: "r"(dst), "l"(src));
}
__device__ __forceinline__ uint32_t f2tf(float x) {
    uint32_t r;
    asm("cvt.rna.tf32.f32 %0, %1;" : "=r"(r) : "f"(x));
    return r;
}
__device__ __forceinline__ float roundtf(float x) { return __uint_as_float(f2tf(x)); }
__device__ __forceinline__ void mma_tf32(float* c, const uint32_t* a, const uint32_t* b) {
    asm volatile("mma.sync.aligned.m16n8k8.row.col.f32.tf32.tf32.f32 "
                 "{%0,%1,%2,%3}, {%4,%5,%6,%7}, {%8,%9}, {%0,%1,%2,%3};"
                 : "+f"(c[0]), "+f"(c[1]), "+f"(c[2]), "+f"(c[3])
                 : "r"(a[0]), "r"(a[1]), "r"(a[2]), "r"(a[3]),
                   "r"(b[0]), "r"(b[1]));
}

// ---------------- tensor-core tf32 GEMM core (R10 config) -------------------
// C[M,N] = A[M,K] @ Bop, 128x128 CTA tile, BK=32, 3-stage cp.async pipeline,
// 4 warps (2x2), warp tile 64x64, double-buffered fragments.
//   BNN=false: Bop = B[N,K]^T (B row-major K-contiguous).
//   BNN=true : Bop = B[K,N]   (B row-major N-contiguous).
// EPI: 0 = plain store (optional tf32 round + alpha)
//      1 = causal-masked exp epilogue: C = roundtf(exp(acc)) (or 0 above the
//          diagonal when diag), plus per-row partial sums written to ps[t].
//      2 = row-rescale epilogue: C = acc / rowsum, rowsum = sum of psN
//          partials ps[j*SEQ + t].
#define NSTAGE      3
#define STAGE_FLTS  8192          // A 4096 + B 4096 floats (32 KB)
#define GEMM_SMEM   (NSTAGE * STAGE_FLTS * 4)   // 98304 B
#define GTHREADS    128

template<int EPI, bool CVTA, bool ROUND_OUT, bool BNN>
__device__ __forceinline__
void gemm_body(const float* __restrict__ A, const float* __restrict__ B,
               float* __restrict__ C, int ldA, int ldB, int ldC,
               int KT, int bm, int bn, float alphaOut,
               float* __restrict__ ps, int psN, bool diag)
{
    extern __shared__ float sm[];
    const uint32_t sbase = smem_u32(sm);
    const int tid  = threadIdx.x;
    const int lane = tid & 31;
    const int wid  = tid >> 5;        // 0..3
    const int wm = (wid >> 1) * 64;
    const int wn = (wid & 1) * 64;
    const int qr = lane >> 2;         // 0..7
    const int qc = lane & 3;          // 0..3
    const int xm = qr << 2;

    // ---- loader bases (strength-reduced) ----
    const int arow = tid >> 3;            // 0..15
    const int akq  = (tid & 7) * 4;
    const float* Abase = A + (long)(bm * 128 + arow) * ldA + akq;
    const long aStride = (long)16 * ldA;
    const uint32_t adst0 = sbase + (uint32_t)(arow * 32 + (akq ^ ((arow & 7) << 2))) * 4;

    const float* Bbase; long bStride; long bStageStep; uint32_t bdst0;
    if (BNN) {   // tile [k][n], swizzle n^=((k&3)<<3)
        const int bk  = tid >> 5;         // 0..3
        const int bn4 = (tid & 31) * 4;
        Bbase = B + (long)bk * ldB + bn * 128 + bn4;
        bStride = (long)4 * ldB;
        bStageStep = (long)32 * ldB;
        bdst0 = sbase + 16384u + (uint32_t)(bk * 128 + (bn4 ^ ((bk & 3) << 3))) * 4;
    } else {     // tile [n][k], same geometry as A
        Bbase = B + (long)(bn * 128 + arow) * ldB + akq;
        bStride = (long)16 * ldB;
        bStageStep = 32;
        bdst0 = sbase + 16384u + (uint32_t)(arow * 32 + (akq ^ ((arow & 7) << 2))) * 4;
    }

    auto issue_stage = [&](int s) {
        const uint32_t soff = (uint32_t)((s % NSTAGE) * (STAGE_FLTS * 4));
        const float* ap = Abase + s * 32;
        uint32_t ad = adst0 + soff;
#pragma unroll
        for (int t = 0; t < 8; t++) { cpa16(ad, ap); ap += aStride; ad += 2048; }
        const float* bp = Bbase + s * bStageStep;
        uint32_t bd = bdst0 + soff;
#pragma unroll
        for (int t = 0; t < 8; t++) { cpa16(bd, bp); bp += bStride; bd += 2048; }
    };

    // NN fragment column pre-swizzle
    int npr[8];
    if (BNN) {
#pragma unroll
        for (int nt = 0; nt < 8; nt++)
            npr[nt] = (wn + nt * 8 + qr) ^ (qc << 3);
    }

    auto load_frags = [&](const float* As, const float* Bs, int ks,
                          uint32_t af[4][4], uint32_t bf[8][2]) {
        const int k0 = ks * 8;
        const int c0 = (k0 + qc) ^ xm;
        const int c1 = (k0 + 4 + qc) ^ xm;
#pragma unroll
        for (int mt = 0; mt < 4; mt++) {
            int r  = wm + mt * 16 + qr;
            int r8 = r + 8;
            if (CVTA) {
                af[mt][0] = f2tf(As[r  * 32 + c0]);
                af[mt][1] = f2tf(As[r8 * 32 + c0]);
                af[mt][2] = f2tf(As[r  * 32 + c1]);
                af[mt][3] = f2tf(As[r8 * 32 + c1]);
            } else {
                af[mt][0] = __float_as_uint(As[r  * 32 + c0]);
                af[mt][1] = __float_as_uint(As[r8 * 32 + c0]);
                af[mt][2] = __float_as_uint(As[r  * 32 + c1]);
                af[mt][3] = __float_as_uint(As[r8 * 32 + c1]);
            }
        }
#pragma unroll
        for (int nt = 0; nt < 8; nt++) {
            if (BNN) {
                bf[nt][0] = __float_as_uint(Bs[(k0 + qc)     * 128 + npr[nt]]);
                bf[nt][1] = __float_as_uint(Bs[(k0 + 4 + qc) * 128 + npr[nt]]);
            } else {
                int n = wn + nt * 8 + qr;
                bf[nt][0] = __float_as_uint(Bs[n * 32 + c0]);
                bf[nt][1] = __float_as_uint(Bs[n * 32 + c1]);
            }
        }
    };

    float acc[4][8][4];
#pragma unroll
    for (int mt = 0; mt < 4; mt++)
#pragma unroll
        for (int nt = 0; nt < 8; nt++)
#pragma unroll
            for (int i = 0; i < 4; i++) acc[mt][nt][i] = 0.0f;

    auto run_mma = [&](uint32_t af[4][4], uint32_t bf[8][2]) {
#pragma unroll
        for (int mt = 0; mt < 4; mt++)
#pragma unroll
            for (int nt = 0; nt < 8; nt++)
                mma_tf32(acc[mt][nt], af[mt], bf[nt]);
    };

    // prologue: stages 0 and 1
#pragma unroll
    for (int s = 0; s < 2; s++) {
        issue_stage(s);
        asm volatile("cp.async.commit_group;" ::: "memory");
    }

    for (int kt = 0; kt < KT; kt++) {
        asm volatile("cp.async.wait_group 1;" ::: "memory");
        __syncthreads();

        const float* As = sm + (kt % NSTAGE) * STAGE_FLTS;
        const float* Bs = As + 4096;

        uint32_t afA[4][4], bfA[8][2], afB[4][4], bfB[8][2];
        load_frags(As, Bs, 0, afA, bfA);

        int sf = kt + 2;
        if (sf < KT) issue_stage(sf);
        asm volatile("cp.async.commit_group;" ::: "memory");

        load_frags(As, Bs, 1, afB, bfB);
        run_mma(afA, bfA);
        load_frags(As, Bs, 2, afA, bfA);
        run_mma(afB, bfB);
        load_frags(As, Bs, 3, afB, bfB);
        run_mma(afA, bfA);
        run_mma(afB, bfB);
    }

    if (EPI == 1) {
        // ---- causal exp epilogue + per-row partial sums (no atomics) ----
        asm volatile("cp.async.wait_group 0;" ::: "memory");
        __syncthreads();                    // stage reads done; reuse smem
        float* spr = sm;                    // [128 rows][2 warp-halves]
        float rsum[4][2];
#pragma unroll
        for (int mt = 0; mt < 4; mt++) { rsum[mt][0] = 0.0f; rsum[mt][1] = 0.0f; }

#pragma unroll
        for (int mt = 0; mt < 4; mt++) {
            int r0g = bm * 128 + wm + mt * 16 + qr;
#pragma unroll
            for (int nt = 0; nt < 8; nt++) {
                int colg = bn * 128 + wn + nt * 8 + 2 * qc;
                float e0 = 0.f, e1 = 0.f, e2 = 0.f, e3 = 0.f;
                if (!diag || colg     <= r0g)     e0 = __expf(acc[mt][nt][0]);
                if (!diag || colg + 1 <= r0g)     e1 = __expf(acc[mt][nt][1]);
                if (!diag || colg     <= r0g + 8) e2 = __expf(acc[mt][nt][2]);
                if (!diag || colg + 1 <= r0g + 8) e3 = __expf(acc[mt][nt][3]);
                rsum[mt][0] += e0 + e1;
                rsum[mt][1] += e2 + e3;
                *(float2*)&C[(long)r0g * ldC + colg] =
                    make_float2(roundtf(e0), roundtf(e1));
                *(float2*)&C[(long)(r0g + 8) * ldC + colg] =
                    make_float2(roundtf(e2), roundtf(e3));
            }
        }
        // reduce across the 4 qc lanes of each row group
#pragma unroll
        for (int mt = 0; mt < 4; mt++)
#pragma unroll
            for (int h = 0; h < 2; h++) {
                rsum[mt][h] += __shfl_xor_sync(~0u, rsum[mt][h], 1);
                rsum[mt][h] += __shfl_xor_sync(~0u, rsum[mt][h], 2);
            }
        if (qc == 0) {
            int half = wn >> 6;             // 0 or 1
#pragma unroll
            for (int mt = 0; mt < 4; mt++) {
                int lr = wm + mt * 16 + qr;
                spr[lr * 2 + half]       = rsum[mt][0];
                spr[(lr + 8) * 2 + half] = rsum[mt][1];
            }
        }
        __syncthreads();
        if (tid < 128) ps[tid] = spr[tid * 2] + spr[tid * 2 + 1];
        return;
    }

    if (EPI == 2) {
        // ---- rowsum gather + reciprocal ----
        asm volatile("cp.async.wait_group 0;" ::: "memory");
        __syncthreads();
        float* sinv = sm;                   // [128]
        if (tid < 128) {
            float s = 0.0f;
            for (int j = 0; j < psN; j++) s += ps[(long)j * SEQ + tid];
            sinv[tid] = 1.0f / s;
        }
        __syncthreads();
#pragma unroll
        for (int mt = 0; mt < 4; mt++) {
            int lr = wm + mt * 16 + qr;
            int r  = bm * 128 + lr;
            float i0 = sinv[lr], i1 = sinv[lr + 8];
#pragma unroll
            for (int nt = 0; nt < 8; nt++) {
                int col = bn * 128 + wn + nt * 8 + 2 * qc;
                *(float2*)&C[(long)r * ldC + col] =
                    make_float2(acc[mt][nt][0] * i0, acc[mt][nt][1] * i0);
                *(float2*)&C[(long)(r + 8) * ldC + col] =
                    make_float2(acc[mt][nt][2] * i1, acc[mt][nt][3] * i1);
            }
        }
        return;
    }

    // ---- EPI == 0: plain store ----
#pragma unroll
    for (int mt = 0; mt < 4; mt++) {
        int r = bm * 128 + wm + mt * 16 + qr;
#pragma unroll
        for (int nt = 0; nt < 8; nt++) {
            int col = bn * 128 + wn + nt * 8 + 2 * qc;
            float o0 = acc[mt][nt][0] * alphaOut, o1 = acc[mt][nt][1] * alphaOut;
            float o2 = acc[mt][nt][2] * alphaOut, o3 = acc[mt][nt][3] * alphaOut;
            if (ROUND_OUT) { o0 = roundtf(o0); o1 = roundtf(o1);
                             o2 = roundtf(o2); o3 = roundtf(o3); }
            *(float2*)&C[(long)r * ldC + col]       = make_float2(o0, o1);
            *(float2*)&C[(long)(r + 8) * ldC + col] = make_float2(o2, o3);
        }
    }
}

// q/k projections (NN: W[C][H] read directly):
// z=0 (q,Wq)->qp (pre-scaled 2^-5), z=1 (k,Wk)->kp.
__global__ __launch_bounds__(GTHREADS, 2)
void proj_qk(const float* __restrict__ qin, const float* __restrict__ kin,
             const float* __restrict__ Wq, const float* __restrict__ Wk,
             float* __restrict__ qp, float* __restrict__ kp)
{
    const float* A; const float* B; float* C; float alpha = 1.0f;
    if (blockIdx.z == 0) { A = qin; B = Wq; C = qp; alpha = 1.0f / 32.0f; }
    else                 { A = kin; B = Wk; C = kp; }
    gemm_body<0, true, true, true>(A, B, C, CIN, HID, HID, CIN / 32,
                                   blockIdx.y, blockIdx.x, alpha,
                                   nullptr, 0, false);
}

// v projection on the low-priority side stream. vp = v @ Wq (faithful bug).
__global__ __launch_bounds__(GTHREADS, 2)
void proj_v(const float* __restrict__ vin, const float* __restrict__ Wq,
            float* __restrict__ vp)
{
    gemm_body<0, true, true, true>(vin, Wq, vp, CIN, HID, HID, CIN / 32,
                                   blockIdx.y, blockIdx.x, 1.0f,
                                   nullptr, 0, false);
}

// P' = exp(qp @ kp^T) with causal mask, plus partial row sums.
// Triangular grid, heavy blocks first.
__global__ __launch_bounds__(GTHREADS, 2)
void s_gemm(const float* __restrict__ qp, const float* __restrict__ kp,
            float* __restrict__ P, float* __restrict__ psum)
{
    int idx = 135 - blockIdx.x;           // heavy (high-bm) first
    int acc = 0, bm = 0;
    while (acc + bm + 1 <= idx) { acc += bm + 1; bm++; }
    int bn = idx - acc;
    const int z = blockIdx.z;
    const long ob = (long)z * SEQ * HID;
    float* ps = psum + ((long)z * 16 + bn) * SEQ + bm * 128;
    gemm_body<1, false, false, false>(qp + ob, kp + ob,
                                      P + (long)z * SEQ * SEQ,
                                      HID, HID, SEQ, HID / 32, bm, bn, 1.0f,
                                      ps, 0, bn == bm);
}

// out = (P' @ vp) / rowsum, K causally limited, heavy blocks first.
__global__ __launch_bounds__(GTHREADS, 2)
void pv_gemm(const float* __restrict__ P, const float* __restrict__ vp,
             float* __restrict__ out, const float* __restrict__ psum)
{
    const int bm = (int)(gridDim.y - 1 - blockIdx.y);   // heavy first
    const int bn = blockIdx.x;
    const int z  = blockIdx.z;
    const int KT = (bm + 1) * 4;
    float* ps = const_cast<float*>(psum) + (long)z * 16 * SEQ + bm * 128;
    gemm_body<2, false, false, true>(P + (long)z * SEQ * SEQ,
                                     vp + (long)z * SEQ * HID,
                                     out + (long)z * SEQ * HID,
                                     SEQ, HID, HID, KT, bm, bn, 1.0f,
                                     ps, bm + 1, false);
}

// ---------------- launch (fork-join graph: proj_v on a side stream) --------
extern "C" void kernel_launch(void* const* d_in, const int* in_sizes, int n_in,
                              void* d_out, int out_size)
{
    const float* kin = (const float*)d_in[1];
    const float* qin = (const float*)d_in[2];
    const float* vin = (const float*)d_in[3];
    const float* Wk  = (const float*)d_in[4];
    const float* Wq  = (const float*)d_in[5];
    float* out = (float*)d_out;

    float *qp, *kp, *vp, *P, *psum;
    cudaGetSymbolAddress((void**)&qp,   g_qp);
    cudaGetSymbolAddress((void**)&kp,   g_kp);
    cudaGetSymbolAddress((void**)&vp,   g_vp);
    cudaGetSymbolAddress((void**)&P,    g_P);
    cudaGetSymbolAddress((void**)&psum, g_psum);

    cudaFuncSetAttribute(proj_qk, cudaFuncAttributeMaxDynamicSharedMemorySize, GEMM_SMEM);
    cudaFuncSetAttribute(proj_v,  cudaFuncAttributeMaxDynamicSharedMemorySize, GEMM_SMEM);
    cudaFuncSetAttribute(s_gemm,  cudaFuncAttributeMaxDynamicSharedMemorySize, GEMM_SMEM);
    cudaFuncSetAttribute(pv_gemm, cudaFuncAttributeMaxDynamicSharedMemorySize, GEMM_SMEM);

    const int M = BATCH * SEQ;                 // 8192
    dim3 gblk(GTHREADS);

    // side stream (low priority) + events; created per call, never destroyed
    // (few calls total; no device memory held).
    int loPri = 0, hiPri = 0;
    cudaDeviceGetStreamPriorityRange(&loPri, &hiPri);
    cudaStream_t s2;
    cudaStreamCreateWithPriority(&s2, cudaStreamNonBlocking, loPri);
    cudaEvent_t eFork, eJoin;
    cudaEventCreateWithFlags(&eFork, cudaEventDisableTiming);
    cudaEventCreateWithFlags(&eJoin, cudaEventDisableTiming);

    // fork
    cudaEventRecord(eFork, 0);
    cudaStreamWaitEvent(s2, eFork, 0);

    // critical chain
    proj_qk<<<dim3(HID / 128, M / 128, 2), gblk, GEMM_SMEM>>>(qin, kin, Wq, Wk, qp, kp);

    // independent v-projection backfills wave tails
    proj_v<<<dim3(HID / 128, M / 128, 1), gblk, GEMM_SMEM, s2>>>(vin, Wq, vp);
    cudaEventRecord(eJoin, s2);

    // P' = exp(masked logits) + partial row sums (softmax kernel eliminated)
    s_gemm<<<dim3(136, 1, BATCH), gblk, GEMM_SMEM>>>(qp, kp, P, psum);

    // join: pv needs vp
    cudaStreamWaitEvent(0, eJoin, 0);
    pv_gemm<<<dim3(HID / 128, SEQ / 128, BATCH), gblk, GEMM_SMEM>>>(P, vp, out, psum);
}

// round 14
// speedup vs baseline: 1.2113x; 1.0715x over previous
#include <cuda_runtime.h>
#include <cstdint>

#define BATCH 4
#define SEQ   2048
#define CIN   1024
#define HID   1024

// ---------------- scratch (__device__ globals; alloc APIs forbidden) -------
__device__ float g_M   [CIN * CIN];                 // 4 MB  (Wq@Wk^T * 2^-5, tf32)
__device__ float g_qm  [BATCH * SEQ * CIN];         // 32 MB (q@M, tf32-rounded)
__device__ float g_vp  [BATCH * SEQ * HID];         // 32 MB (v@Wq, tf32-rounded)
__device__ float g_P   [(long)BATCH * SEQ * SEQ];   // 64 MB (unnormalized exp'd probs)
__device__ float g_psum[BATCH * 16 * SEQ];          // 512 KB (partial row sums)

// ---------------- helpers ---------------------------------------------------
__device__ __forceinline__ uint32_t smem_u32(const void* p) {
    uint32_t r;
    asm("{ .reg .u64 t; cvta.to.shared.u64 t, %1; cvt.u32.u64 %0, t; }"
        : "=r"(r) : "l"(p));
    return r;
}
__device__ __forceinline__ void cpa16(uint32_t dst, const void* src) {
    asm volatile("cp.async.cg.shared.global [%0], [%1], 16;" :: "r"(dst), "l"(src));
}
__device__ __forceinline__ uint32_t f2tf(float x) {
    uint32_t r;
    asm("cvt.rna.tf32.f32 %0, %1;" : "=r"(r) : "f"(x));
    return r;
}
__device__ __forceinline__ float roundtf(float x) { return __uint_as_float(f2tf(x)); }
__device__ __forceinline__ void mma_tf32(float* c, const uint32_t* a, const uint32_t* b) {
    asm volatile("mma.sync.aligned.m16n8k8.row.col.f32.tf32.tf32.f32 "
                 "{%0,%1,%2,%3}, {%4,%5,%6,%7}, {%8,%9}, {%0,%1,%2,%3};"
                 : "+f"(c[0]), "+f"(c[1]), "+f"(c[2]), "+f"(c[3])
                 : "r"(a[0]), "r"(a[1]), "r"(a[2]), "r"(a[3]),
                   "r"(b[0]), "r"(b[1]));
}

// ---------------- tensor-core tf32 GEMM core (R10 config) -------------------
// C[M,N] = A[M,K] @ Bop, 128x128 CTA tile, BK=32, 3-stage cp.async pipeline,
// 4 warps (2x2), warp tile 64x64, double-buffered fragments.
//   BNN=false: Bop = B[N,K]^T (B row-major K-contiguous).
//   BNN=true : Bop = B[K,N]   (B row-major N-contiguous).
// CVTA/CVTB: RNA-round raw fp32 fragments. EPI as in R13.
#define NSTAGE      3
#define STAGE_FLTS  8192          // A 4096 + B 4096 floats (32 KB)
#define GEMM_SMEM   (NSTAGE * STAGE_FLTS * 4)   // 98304 B
#define GTHREADS    128

template<int EPI, bool CVTA, bool CVTB, bool ROUND_OUT, bool BNN>
__device__ __forceinline__
void gemm_body(const float* __restrict__ A, const float* __restrict__ B,
               float* __restrict__ C, int ldA, int ldB, int ldC,
               int KT, int bm, int bn, float alphaOut,
               float* __restrict__ ps, int psN, bool diag)
{
    extern __shared__ float sm[];
    const uint32_t sbase = smem_u32(sm);
    const int tid  = threadIdx.x;
    const int lane = tid & 31;
    const int wid  = tid >> 5;        // 0..3
    const int wm = (wid >> 1) * 64;
    const int wn = (wid & 1) * 64;
    const int qr = lane >> 2;         // 0..7
    const int qc = lane & 3;          // 0..3
    const int xm = qr << 2;

    // ---- loader bases (strength-reduced) ----
    const int arow = tid >> 3;            // 0..15
    const int akq  = (tid & 7) * 4;
    const float* Abase = A + (long)(bm * 128 + arow) * ldA + akq;
    const long aStride = (long)16 * ldA;
    const uint32_t adst0 = sbase + (uint32_t)(arow * 32 + (akq ^ ((arow & 7) << 2))) * 4;

    const float* Bbase; long bStride; long bStageStep; uint32_t bdst0;
    if (BNN) {   // tile [k][n], swizzle n^=((k&3)<<3)
        const int bk  = tid >> 5;         // 0..3
        const int bn4 = (tid & 31) * 4;
        Bbase = B + (long)bk * ldB + bn * 128 + bn4;
        bStride = (long)4 * ldB;
        bStageStep = (long)32 * ldB;
        bdst0 = sbase + 16384u + (uint32_t)(bk * 128 + (bn4 ^ ((bk & 3) << 3))) * 4;
    } else {     // tile [n][k], same geometry as A
        Bbase = B + (long)(bn * 128 + arow) * ldB + akq;
        bStride = (long)16 * ldB;
        bStageStep = 32;
        bdst0 = sbase + 16384u + (uint32_t)(arow * 32 + (akq ^ ((arow & 7) << 2))) * 4;
    }

    auto issue_stage = [&](int s) {
        const uint32_t soff = (uint32_t)((s % NSTAGE) * (STAGE_FLTS * 4));
        const float* ap = Abase + s * 32;
        uint32_t ad = adst0 + soff;
#pragma unroll
        for (int t = 0; t < 8; t++) { cpa16(ad, ap); ap += aStride; ad += 2048; }
        const float* bp = Bbase + s * bStageStep;
        uint32_t bd = bdst0 + soff;
#pragma unroll
        for (int t = 0; t < 8; t++) { cpa16(bd, bp); bp += bStride; bd += 2048; }
    };

    // NN fragment column pre-swizzle
    int npr[8];
    if (BNN) {
#pragma unroll
        for (int nt = 0; nt < 8; nt++)
            npr[nt] = (wn + nt * 8 + qr) ^ (qc << 3);
    }

    auto load_frags = [&](const float* As, const float* Bs, int ks,
                          uint32_t af[4][4], uint32_t bf[8][2]) {
        const int k0 = ks * 8;
        const int c0 = (k0 + qc) ^ xm;
        const int c1 = (k0 + 4 + qc) ^ xm;
#pragma unroll
        for (int mt = 0; mt < 4; mt++) {
            int r  = wm + mt * 16 + qr;
            int r8 = r + 8;
            if (CVTA) {
                af[mt][0] = f2tf(As[r  * 32 + c0]);
                af[mt][1] = f2tf(As[r8 * 32 + c0]);
                af[mt][2] = f2tf(As[r  * 32 + c1]);
                af[mt][3] = f2tf(As[r8 * 32 + c1]);
            } else {
                af[mt][0] = __float_as_uint(As[r  * 32 + c0]);
                af[mt][1] = __float_as_uint(As[r8 * 32 + c0]);
                af[mt][2] = __float_as_uint(As[r  * 32 + c1]);
                af[mt][3] = __float_as_uint(As[r8 * 32 + c1]);
            }
        }
#pragma unroll
        for (int nt = 0; nt < 8; nt++) {
            if (BNN) {
                float v0 = Bs[(k0 + qc)     * 128 + npr[nt]];
                float v1 = Bs[(k0 + 4 + qc) * 128 + npr[nt]];
                bf[nt][0] = CVTB ? f2tf(v0) : __float_as_uint(v0);
                bf[nt][1] = CVTB ? f2tf(v1) : __float_as_uint(v1);
            } else {
                int n = wn + nt * 8 + qr;
                float v0 = Bs[n * 32 + c0];
                float v1 = Bs[n * 32 + c1];
                bf[nt][0] = CVTB ? f2tf(v0) : __float_as_uint(v0);
                bf[nt][1] = CVTB ? f2tf(v1) : __float_as_uint(v1);
            }
        }
    };

    float acc[4][8][4];
#pragma unroll
    for (int mt = 0; mt < 4; mt++)
#pragma unroll
        for (int nt = 0; nt < 8; nt++)
#pragma unroll
            for (int i = 0; i < 4; i++) acc[mt][nt][i] = 0.0f;

    auto run_mma = [&](uint32_t af[4][4], uint32_t bf[8][2]) {
#pragma unroll
        for (int mt = 0; mt < 4; mt++)
#pragma unroll
            for (int nt = 0; nt < 8; nt++)
                mma_tf32(acc[mt][nt], af[mt], bf[nt]);
    };

    // prologue: stages 0 and 1
#pragma unroll
    for (int s = 0; s < 2; s++) {
        issue_stage(s);
        asm volatile("cp.async.commit_group;" ::: "memory");
    }

    for (int kt = 0; kt < KT; kt++) {
        asm volatile("cp.async.wait_group 1;" ::: "memory");
        __syncthreads();

        const float* As = sm + (kt % NSTAGE) * STAGE_FLTS;
        const float* Bs = As + 4096;

        uint32_t afA[4][4], bfA[8][2], afB[4][4], bfB[8][2];
        load_frags(As, Bs, 0, afA, bfA);

        int sf = kt + 2;
        if (sf < KT) issue_stage(sf);
        asm volatile("cp.async.commit_group;" ::: "memory");

        load_frags(As, Bs, 1, afB, bfB);
        run_mma(afA, bfA);
        load_frags(As, Bs, 2, afA, bfA);
        run_mma(afB, bfB);
        load_frags(As, Bs, 3, afB, bfB);
        run_mma(afA, bfA);
        run_mma(afB, bfB);
    }

    if (EPI == 1) {
        // ---- causal exp epilogue + per-row partial sums (no atomics) ----
        asm volatile("cp.async.wait_group 0;" ::: "memory");
        __syncthreads();                    // stage reads done; reuse smem
        float* spr = sm;                    // [128 rows][2 warp-halves]
        float rsum[4][2];
#pragma unroll
        for (int mt = 0; mt < 4; mt++) { rsum[mt][0] = 0.0f; rsum[mt][1] = 0.0f; }

#pragma unroll
        for (int mt = 0; mt < 4; mt++) {
            int r0g = bm * 128 + wm + mt * 16 + qr;
#pragma unroll
            for (int nt = 0; nt < 8; nt++) {
                int colg = bn * 128 + wn + nt * 8 + 2 * qc;
                float e0 = 0.f, e1 = 0.f, e2 = 0.f, e3 = 0.f;
                if (!diag || colg     <= r0g)     e0 = __expf(acc[mt][nt][0]);
                if (!diag || colg + 1 <= r0g)     e1 = __expf(acc[mt][nt][1]);
                if (!diag || colg     <= r0g + 8) e2 = __expf(acc[mt][nt][2]);
                if (!diag || colg + 1 <= r0g + 8) e3 = __expf(acc[mt][nt][3]);
                rsum[mt][0] += e0 + e1;
                rsum[mt][1] += e2 + e3;
                *(float2*)&C[(long)r0g * ldC + colg] =
                    make_float2(roundtf(e0), roundtf(e1));
                *(float2*)&C[(long)(r0g + 8) * ldC + colg] =
                    make_float2(roundtf(e2), roundtf(e3));
            }
        }
#pragma unroll
        for (int mt = 0; mt < 4; mt++)
#pragma unroll
            for (int h = 0; h < 2; h++) {
                rsum[mt][h] += __shfl_xor_sync(~0u, rsum[mt][h], 1);
                rsum[mt][h] += __shfl_xor_sync(~0u, rsum[mt][h], 2);
            }
        if (qc == 0) {
            int half = wn >> 6;             // 0 or 1
#pragma unroll
            for (int mt = 0; mt < 4; mt++) {
                int lr = wm + mt * 16 + qr;
                spr[lr * 2 + half]       = rsum[mt][0];
                spr[(lr + 8) * 2 + half] = rsum[mt][1];
            }
        }
        __syncthreads();
        if (tid < 128) ps[tid] = spr[tid * 2] + spr[tid * 2 + 1];
        return;
    }

    if (EPI == 2) {
        // ---- rowsum gather + reciprocal ----
        asm volatile("cp.async.wait_group 0;" ::: "memory");
        __syncthreads();
        float* sinv = sm;                   // [128]
        if (tid < 128) {
            float s = 0.0f;
            for (int j = 0; j < psN; j++) s += ps[(long)j * SEQ + tid];
            sinv[tid] = 1.0f / s;
        }
        __syncthreads();
#pragma unroll
        for (int mt = 0; mt < 4; mt++) {
            int lr = wm + mt * 16 + qr;
            int r  = bm * 128 + lr;
            float i0 = sinv[lr], i1 = sinv[lr + 8];
#pragma unroll
            for (int nt = 0; nt < 8; nt++) {
                int col = bn * 128 + wn + nt * 8 + 2 * qc;
                *(float2*)&C[(long)r * ldC + col] =
                    make_float2(acc[mt][nt][0] * i0, acc[mt][nt][1] * i0);
                *(float2*)&C[(long)(r + 8) * ldC + col] =
                    make_float2(acc[mt][nt][2] * i1, acc[mt][nt][3] * i1);
            }
        }
        return;
    }

    // ---- EPI == 0: plain store ----
#pragma unroll
    for (int mt = 0; mt < 4; mt++) {
        int r = bm * 128 + wm + mt * 16 + qr;
#pragma unroll
        for (int nt = 0; nt < 8; nt++) {
            int col = bn * 128 + wn + nt * 8 + 2 * qc;
            float o0 = acc[mt][nt][0] * alphaOut, o1 = acc[mt][nt][1] * alphaOut;
            float o2 = acc[mt][nt][2] * alphaOut, o3 = acc[mt][nt][3] * alphaOut;
            if (ROUND_OUT) { o0 = roundtf(o0); o1 = roundtf(o1);
                             o2 = roundtf(o2); o3 = roundtf(o3); }
            *(float2*)&C[(long)r * ldC + col]       = make_float2(o0, o1);
            *(float2*)&C[(long)(r + 8) * ldC + col] = make_float2(o2, o3);
        }
    }
}

// M = (Wq @ Wk^T) * 2^-5  (NT: both [C,H] row-major, H contiguous)
__global__ __launch_bounds__(GTHREADS, 2)
void m_gemm(const float* __restrict__ Wq, const float* __restrict__ Wk,
            float* __restrict__ M)
{
    gemm_body<0, true, true, true, false>(Wq, Wk, M, HID, HID, CIN, HID / 32,
                                          blockIdx.y, blockIdx.x, 1.0f / 32.0f,
                                          nullptr, 0, false);
}

// qm = q @ M  (NN: M is [c][c'], c' contiguous)
__global__ __launch_bounds__(GTHREADS, 2)
void qm_gemm(const float* __restrict__ qin, const float* __restrict__ M,
             float* __restrict__ qm)
{
    gemm_body<0, true, false, true, true>(qin, M, qm, CIN, CIN, CIN, CIN / 32,
                                          blockIdx.y, blockIdx.x, 1.0f,
                                          nullptr, 0, false);
}

// v projection on the low-priority side stream. vp = v @ Wq (faithful bug).
__global__ __launch_bounds__(GTHREADS, 2)
void proj_v(const float* __restrict__ vin, const float* __restrict__ Wq,
            float* __restrict__ vp)
{
    gemm_body<0, true, false, true, true>(vin, Wq, vp, CIN, HID, HID, CIN / 32,
                                          blockIdx.y, blockIdx.x, 1.0f,
                                          nullptr, 0, false);
}

// P' = exp(qm @ k^T) with causal mask + partial row sums. k is RAW input
// (CVTB rounds fragments). Triangular grid, heavy blocks first.
__global__ __launch_bounds__(GTHREADS, 2)
void s_gemm(const float* __restrict__ qm, const float* __restrict__ kin,
            float* __restrict__ P, float* __restrict__ psum)
{
    int idx = 135 - blockIdx.x;           // heavy (high-bm) first
    int acc = 0, bm = 0;
    while (acc + bm + 1 <= idx) { acc += bm + 1; bm++; }
    int bn = idx - acc;
    const int z = blockIdx.z;
    const long ob = (long)z * SEQ * CIN;
    float* ps = psum + ((long)z * 16 + bn) * SEQ + bm * 128;
    gemm_body<1, false, true, false, false>(qm + ob, kin + ob,
                                            P + (long)z * SEQ * SEQ,
                                            CIN, CIN, SEQ, CIN / 32, bm, bn, 1.0f,
                                            ps, 0, bn == bm);
}

// out = (P' @ vp) / rowsum, K causally limited, heavy blocks first.
__global__ __launch_bounds__(GTHREADS, 2)
void pv_gemm(const float* __restrict__ P, const float* __restrict__ vp,
             float* __restrict__ out, const float* __restrict__ psum)
{
    const int bm = (int)(gridDim.y - 1 - blockIdx.y);   // heavy first
    const int bn = blockIdx.x;
    const int z  = blockIdx.z;
    const int KT = (bm + 1) * 4;
    float* ps = const_cast<float*>(psum) + (long)z * 16 * SEQ + bm * 128;
    gemm_body<2, false, false, false, true>(P + (long)z * SEQ * SEQ,
                                            vp + (long)z * SEQ * HID,
                                            out + (long)z * SEQ * HID,
                                            SEQ, HID, HID, KT, bm, bn, 1.0f,
                                            ps, bm + 1, false);
}

// ---------------- launch (fork-join graph: proj_v on a side stream) --------
extern "C" void kernel_launch(void* const* d_in, const int* in_sizes, int n_in,
                              void* d_out, int out_size)
{
    const float* kin = (const float*)d_in[1];
    const float* qin = (const float*)d_in[2];
    const float* vin = (const float*)d_in[3];
    const float* Wk  = (const float*)d_in[4];
    const float* Wq  = (const float*)d_in[5];
    float* out = (float*)d_out;

    float *M, *qm, *vp, *P, *psum;
    cudaGetSymbolAddress((void**)&M,    g_M);
    cudaGetSymbolAddress((void**)&qm,   g_qm);
    cudaGetSymbolAddress((void**)&vp,   g_vp);
    cudaGetSymbolAddress((void**)&P,    g_P);
    cudaGetSymbolAddress((void**)&psum, g_psum);

    cudaFuncSetAttribute(m_gemm,  cudaFuncAttributeMaxDynamicSharedMemorySize, GEMM_SMEM);
    cudaFuncSetAttribute(qm_gemm, cudaFuncAttributeMaxDynamicSharedMemorySize, GEMM_SMEM);
    cudaFuncSetAttribute(proj_v,  cudaFuncAttributeMaxDynamicSharedMemorySize, GEMM_SMEM);
    cudaFuncSetAttribute(s_gemm,  cudaFuncAttributeMaxDynamicSharedMemorySize, GEMM_SMEM);
    cudaFuncSetAttribute(pv_gemm, cudaFuncAttributeMaxDynamicSharedMemorySize, GEMM_SMEM);

    const int Mrows = BATCH * SEQ;             // 8192
    dim3 gblk(GTHREADS);

    // side stream (low priority) + events; created per call, never destroyed
    // (few calls total; no device memory held).
    int loPri = 0, hiPri = 0;
    cudaDeviceGetStreamPriorityRange(&loPri, &hiPri);
    cudaStream_t s2;
    cudaStreamCreateWithPriority(&s2, cudaStreamNonBlocking, loPri);
    cudaEvent_t eFork, eJoin;
    cudaEventCreateWithFlags(&eFork, cudaEventDisableTiming);
    cudaEventCreateWithFlags(&eJoin, cudaEventDisableTiming);

    // fork
    cudaEventRecord(eFork, 0);
    cudaStreamWaitEvent(s2, eFork, 0);

    // side: v projection (backfills m_gemm/qm_gemm/s_gemm wave tails)
    proj_v<<<dim3(HID / 128, Mrows / 128, 1), gblk, GEMM_SMEM, s2>>>(vin, Wq, vp);
    cudaEventRecord(eJoin, s2);

    // critical chain: M -> qm -> P' (k-projection GEMM eliminated)
    m_gemm <<<dim3(CIN / 128, CIN / 128, 1), gblk, GEMM_SMEM>>>(Wq, Wk, M);
    qm_gemm<<<dim3(CIN / 128, Mrows / 128, 1), gblk, GEMM_SMEM>>>(qin, M, qm);
    s_gemm <<<dim3(136, 1, BATCH), gblk, GEMM_SMEM>>>(qm, kin, P, psum);

    // join: pv needs vp
    cudaStreamWaitEvent(0, eJoin, 0);
    pv_gemm<<<dim3(HID / 128, SEQ / 128, BATCH), gblk, GEMM_SMEM>>>(P, vp, out, psum);
}